// round 1
// baseline (speedup 1.0000x reference)
#include <cuda_runtime.h>

// Problem constants
#define BB 4
#define NN 8192
#define KK 16
#define CC 128
#define BN (BB*NN)
#define TT 3

// Scratch (device globals — allocation-free per harness rules)
__device__ float g_G[BN*CC];       // per-point edge-W1 feature part + b1
__device__ float g_p2[BN*CC];      // per-point U1f * f  (update MLP partial)
__device__ float g_agg[BN*CC];     // max-pooled edge features (+ b2e)
__device__ float g_feat[BN*CC];    // feature ping buffer between iterations
__device__ float g_center[BN*3];   // xyz + delta_xyz

// ---------------------------------------------------------------------------
// Kernel A: per-point matvecs. 384 threads = 3 groups of 128:
//   g0: G[p][i]   = edge_W1f[i,:]·f + edge_b1[i]
//   g1: hoff[i]   = relu(off_W1[i,:]·f + off_b1[i])   (smem)
//   g2: p2[p][i]  = upd_W1f[i,:]·f
// then 3 warps reduce delta = off_W2·hoff + off_b2, center = xyz + delta.
// Weights live in 128 registers/thread; f broadcast from smem via float4.
// ---------------------------------------------------------------------------
__global__ void __launch_bounds__(384, 1) kA(
    const float* __restrict__ fin,
    const float* __restrict__ xyz,
    const float* __restrict__ oW1, const float* __restrict__ ob1,
    const float* __restrict__ oW2, const float* __restrict__ ob2,
    const float* __restrict__ eW1t, const float* __restrict__ eb1t,
    const float* __restrict__ uW1t)
{
    __shared__ __align__(16) float fsm[CC];
    __shared__ float hoff[CC];
    __shared__ float xyzsm[3];
    __shared__ float w2sm[3*CC];
    __shared__ float b2sm[3];

    const float* fsrc = fin ? fin : g_feat;
    const int tid = threadIdx.x;
    const int g = tid >> 7;
    const int row = tid & 127;

    float w[CC];
    float bias = 0.f;
    if (g == 0) {
        #pragma unroll
        for (int c = 0; c < CC; c++) w[c] = eW1t[row*131 + 3 + c];
        bias = eb1t[row];
    } else if (g == 1) {
        #pragma unroll
        for (int c = 0; c < CC; c++) w[c] = oW1[row*CC + c];
        bias = ob1[row];
    } else {
        #pragma unroll
        for (int c = 0; c < CC; c++) w[c] = uW1t[row*256 + 128 + c];
    }
    w2sm[tid] = oW2[tid];            // 3*128 == blockDim
    if (tid < 3) b2sm[tid] = ob2[tid];

    const int per = (BN + gridDim.x - 1) / gridDim.x;
    const int p0 = blockIdx.x * per;
    const int p1 = min(p0 + per, BN);
    if (p0 >= p1) return;

    // prefetch first point
    float fr = 0.f, xr = 0.f;
    if (tid < CC) fr = fsrc[p0*CC + tid];
    else if (tid < CC+3) xr = xyz[p0*3 + (tid - CC)];

    for (int p = p0; p < p1; p++) {
        __syncthreads();
        if (tid < CC) fsm[tid] = fr;
        else if (tid < CC+3) xyzsm[tid-CC] = xr;
        if (p + 1 < p1) {            // prefetch next point during compute
            if (tid < CC) fr = fsrc[(p+1)*CC + tid];
            else if (tid < CC+3) xr = xyz[(p+1)*3 + (tid-CC)];
        }
        __syncthreads();

        float a0 = bias, a1 = 0.f;
        const float4* f4 = (const float4*)fsm;
        #pragma unroll
        for (int cc = 0; cc < CC/4; cc++) {
            float4 v = f4[cc];
            a0 = fmaf(w[4*cc+0], v.x, a0);
            a1 = fmaf(w[4*cc+1], v.y, a1);
            a0 = fmaf(w[4*cc+2], v.z, a0);
            a1 = fmaf(w[4*cc+3], v.w, a1);
        }
        float acc = a0 + a1;
        if (g == 0)      g_G[p*CC + row] = acc;
        else if (g == 1) hoff[row] = fmaxf(acc, 0.f);
        else             g_p2[p*CC + row] = acc;
        __syncthreads();

        if (tid < 96) {              // warps 0..2: delta_xyz reduce
            int d = tid >> 5, lane = tid & 31;
            float s = 0.f;
            #pragma unroll
            for (int c = 0; c < 4; c++)
                s = fmaf(w2sm[d*CC + lane + 32*c], hoff[lane + 32*c], s);
            #pragma unroll
            for (int off = 16; off > 0; off >>= 1)
                s += __shfl_xor_sync(0xffffffffu, s, off);
            if (lane == 0) g_center[p*3 + d] = xyzsm[d] + s + b2sm[d];
        }
    }
}

// ---------------------------------------------------------------------------
// Kernel B: per-point edge MLP + max-pool. 128 threads, thread i owns
// edge_W2 row i (128 regs) + edge_W1 position row (3 regs).
//   hidden[k][i] = relu(G[j_k][i] + W1p[i,:]·rel_k)     (smem, k-major)
//   agg[i] = max_k ( W2[i,:]·hidden[k] ) + b2e[i]
// Matvec reads hidden as float4 smem broadcasts: 1 LDS.128 per 4 FFMA.
// ---------------------------------------------------------------------------
__global__ void __launch_bounds__(128, 3) kB(
    const float* __restrict__ xyz,
    const int* __restrict__ knn,
    const float* __restrict__ eW1t,
    const float* __restrict__ eW2t,
    const float* __restrict__ eb2t)
{
    __shared__ int sj[KK];
    __shared__ float relsm[KK*3];
    __shared__ float centsm[3];
    __shared__ __align__(16) float hid[KK*CC];

    const int tid = threadIdx.x;
    float w2[CC];
    #pragma unroll
    for (int c = 0; c < CC; c++) w2[c] = eW2t[tid*CC + c];
    const float wp0 = eW1t[tid*131 + 0];
    const float wp1 = eW1t[tid*131 + 1];
    const float wp2 = eW1t[tid*131 + 2];
    const float b2  = eb2t[tid];

    const int per = (BN + gridDim.x - 1) / gridDim.x;
    const int p0 = blockIdx.x * per;
    const int p1 = min(p0 + per, BN);
    if (p0 >= p1) return;

    int sjr = 0; float centr = 0.f;
    if (tid < KK) sjr = knn[p0*KK + tid];
    else if (tid < KK+3) centr = g_center[p0*3 + (tid-KK)];

    for (int p = p0; p < p1; p++) {
        const int bbase = (p >> 13) << 13;   // batch * N
        __syncthreads();
        if (tid < KK) sj[tid] = sjr;
        else if (tid < KK+3) centsm[tid-KK] = centr;
        if (p + 1 < p1) {                    // prefetch next point's idx/center
            if (tid < KK) sjr = knn[(p+1)*KK + tid];
            else if (tid < KK+3) centr = g_center[(p+1)*3 + (tid-KK)];
        }
        __syncthreads();

        if (tid < 48) {
            int k = tid / 3, d = tid - 3*k;
            relsm[tid] = xyz[(bbase + sj[k])*3 + d] - centsm[d];
        }
        float gv[KK];
        #pragma unroll
        for (int k = 0; k < KK; k++)
            gv[k] = g_G[(bbase + sj[k])*CC + tid];
        __syncthreads();

        #pragma unroll
        for (int k = 0; k < KK; k++) {
            float h = fmaf(wp0, relsm[3*k+0],
                      fmaf(wp1, relsm[3*k+1],
                      fmaf(wp2, relsm[3*k+2], gv[k])));
            hid[k*CC + tid] = fmaxf(h, 0.f);
        }
        __syncthreads();

        float agg = -3.402823466e38f;
        const float4* h4 = (const float4*)hid;
        for (int k = 0; k < KK; k++) {       // rolled: keeps I-footprint small
            float e0 = 0.f, e1 = 0.f;
            #pragma unroll
            for (int cc = 0; cc < CC/4; cc++) {
                float4 v = h4[k*(CC/4) + cc];
                e0 = fmaf(w2[4*cc+0], v.x, e0);
                e1 = fmaf(w2[4*cc+1], v.y, e1);
                e0 = fmaf(w2[4*cc+2], v.z, e0);
                e1 = fmaf(w2[4*cc+3], v.w, e1);
            }
            agg = fmaxf(agg, e0 + e1);
        }
        g_agg[p*CC + tid] = agg + b2;
    }
}

// ---------------------------------------------------------------------------
// Kernel C: update MLP. 256 threads = 2 groups of 128, software-pipelined:
//   g0 (point p):   h[i] = relu(U1a[i,:]·agg + b1u[i] + p2[p][i])
//   g1 (point p-1): out[i] = f[i] + U2[i,:]·h + b2u[i]
// Double-buffered smem; one block barrier per point + a named barrier
// (threads 0..127 only) between g0's loads and its broadcast reads.
// ---------------------------------------------------------------------------
__global__ void __launch_bounds__(256, 1) kC(
    const float* __restrict__ fin,
    const float* __restrict__ uW1t, const float* __restrict__ ub1t,
    const float* __restrict__ uW2t, const float* __restrict__ ub2t,
    float* __restrict__ fout)
{
    __shared__ __align__(16) float aggsm[2][CC];
    __shared__ __align__(16) float fsm[2][CC];
    __shared__ __align__(16) float hsm[2][CC];

    const float* fsrc = fin ? fin : g_feat;
    float* fdst = fout ? fout : g_feat;

    const int tid = threadIdx.x;
    const int g = tid >> 7;
    const int row = tid & 127;

    float w[CC];
    float bias;
    if (g == 0) {
        #pragma unroll
        for (int c = 0; c < CC; c++) w[c] = uW1t[row*256 + c];   // U1a half
        bias = ub1t[row];
    } else {
        #pragma unroll
        for (int c = 0; c < CC; c++) w[c] = uW2t[row*CC + c];    // U2
        bias = ub2t[row];
    }

    const int per = (BN + gridDim.x - 1) / gridDim.x;
    const int p0 = blockIdx.x * per;
    const int pend = min(p0 + per, BN);
    const int cnt = pend - p0;
    if (cnt <= 0) return;

    float aggr = 0.f, fr = 0.f, p2r = 0.f;
    if (g == 0) {
        aggr = g_agg[p0*CC + row];
        fr   = fsrc[p0*CC + row];
        p2r  = g_p2[p0*CC + row];
    }

    int cur = 0;
    for (int i = 0; i <= cnt; i++) {
        __syncthreads();
        if (g == 0) {
            if (i < cnt) {
                aggsm[cur][row] = aggr;
                fsm[cur][row]   = fr;
                float p2v = p2r;
                if (i + 1 < cnt) {
                    int pn = p0 + i + 1;
                    aggr = g_agg[pn*CC + row];
                    fr   = fsrc[pn*CC + row];
                    p2r  = g_p2[pn*CC + row];
                }
                asm volatile("bar.sync 1, 128;" ::: "memory");
                float a0 = bias, a1 = 0.f;
                const float4* a4 = (const float4*)aggsm[cur];
                #pragma unroll
                for (int cc = 0; cc < CC/4; cc++) {
                    float4 v = a4[cc];
                    a0 = fmaf(w[4*cc+0], v.x, a0);
                    a1 = fmaf(w[4*cc+1], v.y, a1);
                    a0 = fmaf(w[4*cc+2], v.z, a0);
                    a1 = fmaf(w[4*cc+3], v.w, a1);
                }
                hsm[cur][row] = fmaxf(a0 + a1 + p2v, 0.f);
            }
        } else {
            if (i > 0) {
                int prev = cur ^ 1;
                float a0 = bias, a1 = 0.f;
                const float4* h4 = (const float4*)hsm[prev];
                #pragma unroll
                for (int cc = 0; cc < CC/4; cc++) {
                    float4 v = h4[cc];
                    a0 = fmaf(w[4*cc+0], v.x, a0);
                    a1 = fmaf(w[4*cc+1], v.y, a1);
                    a0 = fmaf(w[4*cc+2], v.z, a0);
                    a1 = fmaf(w[4*cc+3], v.w, a1);
                }
                fdst[(p0 + i - 1)*CC + row] = fsm[prev][row] + a0 + a1;
            }
        }
        cur ^= 1;
    }
}

// ---------------------------------------------------------------------------
extern "C" void kernel_launch(void* const* d_in, const int* in_sizes, int n_in,
                              void* d_out, int out_size)
{
    const float* xyz  = (const float*)d_in[0];
    const float* feat = (const float*)d_in[1];
    const int*   knn  = (const int*)d_in[2];
    const float* oW1  = (const float*)d_in[3];
    const float* ob1  = (const float*)d_in[4];
    const float* oW2  = (const float*)d_in[5];
    const float* ob2  = (const float*)d_in[6];
    const float* eW1  = (const float*)d_in[7];
    const float* eb1  = (const float*)d_in[8];
    const float* eW2  = (const float*)d_in[9];
    const float* eb2  = (const float*)d_in[10];
    const float* uW1  = (const float*)d_in[11];
    const float* ub1  = (const float*)d_in[12];
    const float* uW2  = (const float*)d_in[13];
    const float* ub2  = (const float*)d_in[14];
    float* out = (float*)d_out;

    for (int t = 0; t < TT; t++) {
        const float* fin_t = (t == 0) ? feat : nullptr;       // nullptr -> g_feat
        kA<<<152, 384>>>(fin_t, xyz, oW1, ob1, oW2, ob2,
                         eW1 + t*CC*131, eb1 + t*CC, uW1 + t*CC*256);
        kB<<<456, 128>>>(xyz, knn, eW1 + t*CC*131,
                         eW2 + t*CC*CC, eb2 + t*CC);
        float* fout_t = (t == TT-1) ? out : nullptr;          // nullptr -> g_feat
        kC<<<152, 256>>>(fin_t, uW1 + t*CC*256, ub1 + t*CC,
                         uW2 + t*CC*CC, ub2 + t*CC, fout_t);
    }
}

// round 8
// speedup vs baseline: 1.0413x; 1.0413x over previous
#include <cuda_runtime.h>

// Problem constants
#define BB 4
#define NN 8192
#define KK 16
#define CC 128
#define BN (BB*NN)
#define TT 3

typedef unsigned long long u64;

// Packed f32x2 helpers (Blackwell-only; ptxas never emits FFMA2 from C++)
__device__ __forceinline__ u64 pk2(float lo, float hi){
    u64 r; asm("mov.b64 %0, {%1,%2};" : "=l"(r) : "f"(lo), "f"(hi)); return r;
}
__device__ __forceinline__ void fma2(u64 &d, u64 a, u64 b){
    asm("fma.rn.f32x2 %0, %1, %2, %0;" : "+l"(d) : "l"(a), "l"(b));
}
__device__ __forceinline__ float2 up2(u64 v){
    float2 f; asm("mov.b64 {%0,%1}, %2;" : "=f"(f.x), "=f"(f.y) : "l"(v)); return f;
}

// Scratch (device globals — allocation-free per harness rules)
__device__ float g_G[BN*CC];       // per-point edge-W1 feature part + b1
__device__ float g_p2[BN*CC];      // per-point U1f * f
__device__ float g_agg[BN*CC];     // max-pooled edge features (+ b2e)
__device__ float g_feat[BN*CC];    // feature ping buffer between iterations
__device__ float g_center[BN*3];   // xyz + delta_xyz

// ---------------------------------------------------------------------------
// Kernel A: per-point matvecs, 4 points per barrier round.
// 384 threads = 3 groups of 128 (G rows / offset hidden / upd partial).
// Packed FFMA2 matvecs; activations broadcast from smem as ulonglong2.
// ---------------------------------------------------------------------------
__global__ void __launch_bounds__(384, 1) kA(
    const float* __restrict__ fin,
    const float* __restrict__ xyz,
    const float* __restrict__ oW1, const float* __restrict__ ob1,
    const float* __restrict__ oW2, const float* __restrict__ ob2,
    const float* __restrict__ eW1t, const float* __restrict__ eb1t,
    const float* __restrict__ uW1t)
{
    __shared__ __align__(16) float fsm[4][CC];
    __shared__ float hoff[4][CC];
    __shared__ float xyzsm[12];
    __shared__ float w2sm[3*CC];
    __shared__ float b2sm[3];

    const float* fsrc = fin ? fin : g_feat;
    const int tid = threadIdx.x;
    const int g = tid >> 7;
    const int row = tid & 127;

    u64 w[CC/2];
    float bias = 0.f;
    if (g == 0) {                    // edge W1 feature half (stride 131: pack manually)
        #pragma unroll
        for (int c = 0; c < CC/2; c++)
            w[c] = pk2(eW1t[row*131 + 3 + 2*c], eW1t[row*131 + 4 + 2*c]);
        bias = eb1t[row];
    } else if (g == 1) {
        const ulonglong2* ws = (const ulonglong2*)(oW1 + row*CC);
        #pragma unroll
        for (int c = 0; c < CC/4; c++){ ulonglong2 t = ws[c]; w[2*c] = t.x; w[2*c+1] = t.y; }
        bias = ob1[row];
    } else {
        const ulonglong2* ws = (const ulonglong2*)(uW1t + row*256 + 128);
        #pragma unroll
        for (int c = 0; c < CC/4; c++){ ulonglong2 t = ws[c]; w[2*c] = t.x; w[2*c+1] = t.y; }
    }
    w2sm[tid] = oW2[tid];            // 3*128 == blockDim
    if (tid < 3) b2sm[tid] = ob2[tid];

    const int per = (BN + gridDim.x - 1) / gridDim.x;
    const int p0 = blockIdx.x * per;
    const int p1 = min(p0 + per, BN);
    if (p0 >= p1) return;

    // prefetch round 0
    float fr[4]; float xr = 0.f;
    if (tid < CC) {
        #pragma unroll
        for (int j = 0; j < 4; j++){ int p = min(p0+j, BN-1); fr[j] = fsrc[p*CC + tid]; }
    } else if (tid < CC+12) {
        int q = tid - CC; int p = min(p0 + q/3, BN-1); xr = xyz[p*3 + q%3];
    }

    for (int base = p0; base < p1; base += 4) {
        __syncthreads();
        if (tid < CC) {
            #pragma unroll
            for (int j = 0; j < 4; j++) fsm[j][tid] = fr[j];
        } else if (tid < CC+12) {
            xyzsm[tid-CC] = xr;
        }
        if (base + 4 < p1) {         // prefetch next round
            if (tid < CC) {
                #pragma unroll
                for (int j = 0; j < 4; j++){ int p = min(base+4+j, BN-1); fr[j] = fsrc[p*CC + tid]; }
            } else if (tid < CC+12) {
                int q = tid - CC; int p = min(base+4 + q/3, BN-1); xr = xyz[p*3 + q%3];
            }
        }
        __syncthreads();

        float val[4];
        #pragma unroll
        for (int j = 0; j < 4; j++) {
            u64 a0 = pk2(bias, 0.f), a1 = 0ULL;
            const ulonglong2* f2 = (const ulonglong2*)fsm[j];
            #pragma unroll
            for (int c = 0; c < CC/4; c++) {
                ulonglong2 v = f2[c];
                fma2(a0, w[2*c],   v.x);
                fma2(a1, w[2*c+1], v.y);
            }
            float2 s0 = up2(a0), s1 = up2(a1);
            val[j] = (s0.x + s0.y) + (s1.x + s1.y);
        }
        #pragma unroll
        for (int j = 0; j < 4; j++) {
            int p = base + j;
            if (p < p1) {
                if (g == 0)      g_G[p*CC + row] = val[j];
                else if (g == 1) hoff[j][row] = fmaxf(val[j], 0.f);
                else             g_p2[p*CC + row] = val[j];
            }
        }
        __syncthreads();

        // 12 warps: warp w -> point j = w&3, dim d = w>>2 (0..2)
        {
            int wrp = tid >> 5, lane = tid & 31;
            int j = wrp & 3, d = wrp >> 2;
            if (base + j < p1) {
                float s = 0.f;
                #pragma unroll
                for (int c = 0; c < 4; c++)
                    s = fmaf(w2sm[d*CC + lane + 32*c], hoff[j][lane + 32*c], s);
                #pragma unroll
                for (int off = 16; off > 0; off >>= 1)
                    s += __shfl_xor_sync(0xffffffffu, s, off);
                if (lane == 0) g_center[(base+j)*3 + d] = xyzsm[j*3+d] + s + b2sm[d];
            }
        }
    }
}

// ---------------------------------------------------------------------------
// Kernel B: per-point edge MLP + max-pool, packed FFMA2, deep prefetch.
// Thread i owns edge_W2 row i (64 packed regs) + W1 position row.
// Next point's knn/G/xyz/center prefetched into regs during the matvec.
// ---------------------------------------------------------------------------
__global__ void __launch_bounds__(128, 2) kB(
    const float* __restrict__ xyz,
    const int* __restrict__ knn,
    const float* __restrict__ eW1t,
    const float* __restrict__ eW2t,
    const float* __restrict__ eb2t)
{
    __shared__ __align__(16) float hid[KK*CC];

    const int tid = threadIdx.x;
    u64 w[CC/2];
    {
        const ulonglong2* ws = (const ulonglong2*)(eW2t + tid*CC);
        #pragma unroll
        for (int c = 0; c < CC/4; c++){ ulonglong2 t = ws[c]; w[2*c] = t.x; w[2*c+1] = t.y; }
    }
    const float wp0 = eW1t[tid*131 + 0];
    const float wp1 = eW1t[tid*131 + 1];
    const float wp2 = eW1t[tid*131 + 2];
    const float b2  = eb2t[tid];

    const int per = (BN + gridDim.x - 1) / gridDim.x;
    const int p0 = blockIdx.x * per;
    const int p1 = min(p0 + per, BN);
    if (p0 >= p1) return;

    float gv[KK], nx[KK], ny[KK], nz[KK], cx, cy, cz;
    {   // prefetch point p0
        const int bbase = (p0 >> 13) << 13;
        int j[KK];
        #pragma unroll
        for (int k = 0; k < KK; k++) j[k] = bbase + __ldg(&knn[p0*KK + k]);
        #pragma unroll
        for (int k = 0; k < KK; k++) {
            gv[k] = __ldg(&g_G[j[k]*CC + tid]);
            nx[k] = __ldg(&xyz[j[k]*3 + 0]);
            ny[k] = __ldg(&xyz[j[k]*3 + 1]);
            nz[k] = __ldg(&xyz[j[k]*3 + 2]);
        }
        cx = __ldg(&g_center[p0*3+0]); cy = __ldg(&g_center[p0*3+1]); cz = __ldg(&g_center[p0*3+2]);
    }

    for (int p = p0; p < p1; p++) {
        // hidden(p): h[k] = relu(G[j_k] + wp·nbr_k - wp·center)
        float pc = fmaf(wp0, cx, fmaf(wp1, cy, wp2*cz));
        #pragma unroll
        for (int k = 0; k < KK; k++) {
            float h = fmaf(wp0, nx[k], fmaf(wp1, ny[k], fmaf(wp2, nz[k], gv[k] - pc)));
            hid[k*CC + tid] = fmaxf(h, 0.f);
        }
        __syncthreads();

        // prefetch p+1 (consumed next iteration; hides L2 latency under matvec)
        if (p + 1 < p1) {
            const int pn = p + 1;
            const int bbase = (pn >> 13) << 13;
            int j[KK];
            #pragma unroll
            for (int k = 0; k < KK; k++) j[k] = bbase + __ldg(&knn[pn*KK + k]);
            #pragma unroll
            for (int k = 0; k < KK; k++) {
                gv[k] = __ldg(&g_G[j[k]*CC + tid]);
                nx[k] = __ldg(&xyz[j[k]*3 + 0]);
                ny[k] = __ldg(&xyz[j[k]*3 + 1]);
                nz[k] = __ldg(&xyz[j[k]*3 + 2]);
            }
            cx = __ldg(&g_center[pn*3+0]); cy = __ldg(&g_center[pn*3+1]); cz = __ldg(&g_center[pn*3+2]);
        }

        // matvec + max-pool (packed): per k, 32 LDS.128 + 64 FFMA2
        float agg = -3.402823466e38f;
        #pragma unroll 2
        for (int k = 0; k < KK; k++) {
            u64 a0 = 0ULL, a1 = 0ULL;
            const ulonglong2* h2 = (const ulonglong2*)(hid + k*CC);
            #pragma unroll
            for (int c = 0; c < CC/4; c++) {
                ulonglong2 v = h2[c];
                fma2(a0, w[2*c],   v.x);
                fma2(a1, w[2*c+1], v.y);
            }
            float2 s0 = up2(a0), s1 = up2(a1);
            agg = fmaxf(agg, (s0.x + s0.y) + (s1.x + s1.y));
        }
        g_agg[p*CC + tid] = agg + b2;
        __syncthreads();               // before next hidden overwrites hid
    }
}

// ---------------------------------------------------------------------------
// Kernel C: update MLP, 2-stage pipeline, packed FFMA2.
//   g0 (point p):   h = relu(U1a·agg + b1u + p2[p])
//   g1 (point p-1): out = f + U2·h + b2u
// ---------------------------------------------------------------------------
__global__ void __launch_bounds__(256, 1) kC(
    const float* __restrict__ fin,
    const float* __restrict__ uW1t, const float* __restrict__ ub1t,
    const float* __restrict__ uW2t, const float* __restrict__ ub2t,
    float* __restrict__ fout)
{
    __shared__ __align__(16) float aggsm[2][CC];
    __shared__ __align__(16) float fsm[2][CC];
    __shared__ __align__(16) float hsm[2][CC];

    const float* fsrc = fin ? fin : g_feat;
    float* fdst = fout ? fout : g_feat;

    const int tid = threadIdx.x;
    const int g = tid >> 7;
    const int row = tid & 127;

    u64 w[CC/2];
    float bias;
    if (g == 0) {
        const ulonglong2* ws = (const ulonglong2*)(uW1t + row*256);   // U1a half
        #pragma unroll
        for (int c = 0; c < CC/4; c++){ ulonglong2 t = ws[c]; w[2*c] = t.x; w[2*c+1] = t.y; }
        bias = ub1t[row];
    } else {
        const ulonglong2* ws = (const ulonglong2*)(uW2t + row*CC);    // U2
        #pragma unroll
        for (int c = 0; c < CC/4; c++){ ulonglong2 t = ws[c]; w[2*c] = t.x; w[2*c+1] = t.y; }
        bias = ub2t[row];
    }

    const int per = (BN + gridDim.x - 1) / gridDim.x;
    const int p0 = blockIdx.x * per;
    const int pend = min(p0 + per, BN);
    const int cnt = pend - p0;
    if (cnt <= 0) return;

    float aggr = 0.f, fr = 0.f, p2r = 0.f;
    if (g == 0) {
        aggr = g_agg[p0*CC + row];
        fr   = fsrc[p0*CC + row];
        p2r  = g_p2[p0*CC + row];
    }

    int cur = 0;
    for (int i = 0; i <= cnt; i++) {
        __syncthreads();
        if (g == 0) {
            if (i < cnt) {
                aggsm[cur][row] = aggr;
                fsm[cur][row]   = fr;
                float p2v = p2r;
                if (i + 1 < cnt) {
                    int pn = p0 + i + 1;
                    aggr = g_agg[pn*CC + row];
                    fr   = fsrc[pn*CC + row];
                    p2r  = g_p2[pn*CC + row];
                }
                asm volatile("bar.sync 1, 128;" ::: "memory");
                u64 a0 = pk2(bias, 0.f), a1 = 0ULL;
                const ulonglong2* a4 = (const ulonglong2*)aggsm[cur];
                #pragma unroll
                for (int c = 0; c < CC/4; c++) {
                    ulonglong2 v = a4[c];
                    fma2(a0, w[2*c],   v.x);
                    fma2(a1, w[2*c+1], v.y);
                }
                float2 s0 = up2(a0), s1 = up2(a1);
                hsm[cur][row] = fmaxf((s0.x + s0.y) + (s1.x + s1.y) + p2v, 0.f);
            }
        } else {
            if (i > 0) {
                int prev = cur ^ 1;
                u64 a0 = pk2(bias, 0.f), a1 = 0ULL;
                const ulonglong2* h4 = (const ulonglong2*)hsm[prev];
                #pragma unroll
                for (int c = 0; c < CC/4; c++) {
                    ulonglong2 v = h4[c];
                    fma2(a0, w[2*c],   v.x);
                    fma2(a1, w[2*c+1], v.y);
                }
                float2 s0 = up2(a0), s1 = up2(a1);
                fdst[(p0 + i - 1)*CC + row] = fsm[prev][row] + (s0.x + s0.y) + (s1.x + s1.y);
            }
        }
        cur ^= 1;
    }
}

// ---------------------------------------------------------------------------
extern "C" void kernel_launch(void* const* d_in, const int* in_sizes, int n_in,
                              void* d_out, int out_size)
{
    const float* xyz  = (const float*)d_in[0];
    const float* feat = (const float*)d_in[1];
    const int*   knn  = (const int*)d_in[2];
    const float* oW1  = (const float*)d_in[3];
    const float* ob1  = (const float*)d_in[4];
    const float* oW2  = (const float*)d_in[5];
    const float* ob2  = (const float*)d_in[6];
    const float* eW1  = (const float*)d_in[7];
    const float* eb1  = (const float*)d_in[8];
    const float* eW2  = (const float*)d_in[9];
    const float* eb2  = (const float*)d_in[10];
    const float* uW1  = (const float*)d_in[11];
    const float* ub1  = (const float*)d_in[12];
    const float* uW2  = (const float*)d_in[13];
    const float* ub2  = (const float*)d_in[14];
    float* out = (float*)d_out;

    for (int t = 0; t < TT; t++) {
        const float* fin_t = (t == 0) ? feat : nullptr;       // nullptr -> g_feat
        kA<<<148, 384>>>(fin_t, xyz, oW1, ob1, oW2, ob2,
                         eW1 + t*CC*131, eb1 + t*CC, uW1 + t*CC*256);
        kB<<<296, 128>>>(xyz, knn, eW1 + t*CC*131,
                         eW2 + t*CC*CC, eb2 + t*CC);
        float* fout_t = (t == TT-1) ? out : nullptr;          // nullptr -> g_feat
        kC<<<148, 256>>>(fin_t, uW1 + t*CC*256, ub1 + t*CC,
                         uW2 + t*CC*CC, ub2 + t*CC, fout_t);
    }
}